// round 3
// baseline (speedup 1.0000x reference)
#include <cuda_runtime.h>
#include <math.h>

#define BDIM 2
#define NPTS 16384
#define KNB 32
#define CCH 64
#define GDIM 10
#define PPB 4          // points per block
#define NTHREADS 256
#define H1S 65         // padded h1 row stride (conflict-free GEMM reads)
#define WOS 65         // padded W_out row stride
#define EPSF 1e-5f

struct Smem {
  float Wp[CCH][GDIM];       // folded a1 * W_pos
  float bias1[CCH];
  float a1s[CCH];
  float a2s[CCH];
  float Wg[CCH][CCH];        // Wg[c][d] = a2[d] * W_gcm[d][c]  (transposed + folded)
  float bias2[CCH];
  float Wout[CCH][WOS];      // [o][c], padded
  float bout[CCH];
  float lng[CCH];
  float lnb[CCH];
  float Watt[KNB];
  float h1[PPB][KNB * H1S];
  float sarr[PPB][CCH];
  float marr[PPB][CCH];
  float resv[PPB][CCH];
  float redA[PPB][2];
  float redB[PPB][2];
  float redC[PPB][2];
  float redD[PPB][2];
};

__global__ __launch_bounds__(NTHREADS, 3)
void bridgenet_kernel(
    const float* __restrict__ points,
    const float* __restrict__ features,
    const int*   __restrict__ gidx,
    const float* __restrict__ W_pos,
    const float* __restrict__ b_pos,
    const float* __restrict__ bn1_g, const float* __restrict__ bn1_b,
    const float* __restrict__ bn1_m, const float* __restrict__ bn1_v,
    const float* __restrict__ W_gcm,
    const float* __restrict__ b_gcm,
    const float* __restrict__ bn2_g, const float* __restrict__ bn2_b,
    const float* __restrict__ bn2_m, const float* __restrict__ bn2_v,
    const float* __restrict__ W_att,
    const float* __restrict__ W_out,
    const float* __restrict__ b_out,
    const float* __restrict__ ln_g, const float* __restrict__ ln_b,
    float* __restrict__ out)
{
  extern __shared__ char smem_raw[];
  Smem& s = *reinterpret_cast<Smem*>(smem_raw);
  const int tid = threadIdx.x;

  // ---------------- Weight load + BN folding (per block) ----------------
  if (tid < CCH) {
    float a1 = bn1_g[tid] * rsqrtf(bn1_v[tid] + EPSF);
    s.a1s[tid]   = a1;
    s.bias1[tid] = a1 * (b_pos[tid] - bn1_m[tid]) + bn1_b[tid];
    float a2 = bn2_g[tid] * rsqrtf(bn2_v[tid] + EPSF);
    s.a2s[tid]   = a2;
    s.bias2[tid] = a2 * (b_gcm[tid] - bn2_m[tid]) + bn2_b[tid];
    s.bout[tid]  = b_out[tid];
    s.lng[tid]   = ln_g[tid];
    s.lnb[tid]   = ln_b[tid];
  }
  if (tid >= CCH && tid < CCH + KNB) s.Watt[tid - CCH] = W_att[tid - CCH];
  __syncthreads();

  for (int i = tid; i < CCH * GDIM; i += NTHREADS) {
    int c = i / GDIM, g = i - c * GDIM;
    s.Wp[c][g] = s.a1s[c] * W_pos[i];
  }
  for (int i = tid; i < CCH * CCH; i += NTHREADS) {
    int c = i >> 6, d = i & 63;
    s.Wg[c][d] = s.a2s[d] * W_gcm[d * CCH + c];
    s.Wout[c][d] = W_out[i];   // c here is the o-row of W_out (same decomposition)
  }
  __syncthreads();

  const int pt = tid >> 6;           // 0..3 : point within block
  const int tp = tid & 63;           // thread within point
  const int p  = blockIdx.x * PPB + pt;
  const int bb = p >> 14;            // N = 16384 = 2^14
  const int nn = p & (NPTS - 1);
  const int base_pn = bb * NPTS + nn;

  // ---------------- Phase 1: gather + position encoding -> h1 in SMEM ----
  {
    const int k    = tp >> 1;
    const int half = tp & 1;
    const int coff = half * 32;
    const int idx  = gidx[base_pn * KNB + k];
    const int gb   = bb * NPTS + idx;

    const float xix = points[base_pn * 3 + 0];
    const float xiy = points[base_pn * 3 + 1];
    const float xiz = points[base_pn * 3 + 2];
    const float gx  = points[gb * 3 + 0];
    const float gy  = points[gb * 3 + 1];
    const float gz  = points[gb * 3 + 2];
    const float dx = xix - gx, dy = xiy - gy, dz = xiz - gz;
    const float dist = sqrtf(dx*dx + dy*dy + dz*dz);
    float geo[GDIM] = {xix, xiy, xiz, gx, gy, gz, dx, dy, dz, dist};

    const float4* fp4 = reinterpret_cast<const float4*>(features + gb * CCH + coff);
    float4 f[8];
    #pragma unroll
    for (int j = 0; j < 8; ++j) f[j] = fp4[j];

    float* h1row = &s.h1[pt][k * H1S + coff];
    #pragma unroll
    for (int j = 0; j < 8; ++j) {
      float fv[4] = {f[j].x, f[j].y, f[j].z, f[j].w};
      #pragma unroll
      for (int q = 0; q < 4; ++q) {
        const int c = coff + j * 4 + q;
        float e = s.bias1[c];
        #pragma unroll
        for (int g = 0; g < GDIM; ++g) e = fmaf(geo[g], s.Wp[c][g], e);
        e = fmaxf(e, 0.0f);
        h1row[j * 4 + q] = e + fv[q];
      }
    }
  }
  __syncthreads();

  // ---------------- Phase 2: h2 = relu(bn2(h1 @ W_gcm^T)); att + max ------
  {
    const int kt = tp & 7;           // k-tile (4 rows each)
    const int dt = tp >> 3;          // d-tile (8 cols each)
    const float* h1base = &s.h1[pt][kt * 4 * H1S];

    float acc[4][8];
    #pragma unroll
    for (int kk = 0; kk < 4; ++kk)
      #pragma unroll
      for (int j = 0; j < 8; ++j) acc[kk][j] = 0.0f;

    #pragma unroll 4
    for (int c = 0; c < CCH; ++c) {
      const float4 w0 = *reinterpret_cast<const float4*>(&s.Wg[c][dt * 8]);
      const float4 w1 = *reinterpret_cast<const float4*>(&s.Wg[c][dt * 8 + 4]);
      const float wv[8] = {w0.x, w0.y, w0.z, w0.w, w1.x, w1.y, w1.z, w1.w};
      const float hv[4] = {h1base[c], h1base[H1S + c],
                           h1base[2 * H1S + c], h1base[3 * H1S + c]};
      #pragma unroll
      for (int kk = 0; kk < 4; ++kk)
        #pragma unroll
        for (int j = 0; j < 8; ++j)
          acc[kk][j] = fmaf(hv[kk], wv[j], acc[kk][j]);
    }

    const float w0 = s.Watt[kt * 4 + 0];
    const float w1 = s.Watt[kt * 4 + 1];
    const float w2 = s.Watt[kt * 4 + 2];
    const float w3 = s.Watt[kt * 4 + 3];

    float sp[8], mp[8];
    #pragma unroll
    for (int j = 0; j < 8; ++j) {
      const float b2 = s.bias2[dt * 8 + j];
      const float h20 = fmaxf(acc[0][j] + b2, 0.0f);
      const float h21 = fmaxf(acc[1][j] + b2, 0.0f);
      const float h22 = fmaxf(acc[2][j] + b2, 0.0f);
      const float h23 = fmaxf(acc[3][j] + b2, 0.0f);
      sp[j] = h20 * w0 + h21 * w1 + h22 * w2 + h23 * w3;
      mp[j] = fmaxf(fmaxf(h20, h21), fmaxf(h22, h23));  // all >= 0
    }

    // reduce across the 8 k-tiles (lanes differing in low 3 bits)
    #pragma unroll
    for (int msk = 1; msk <= 4; msk <<= 1) {
      #pragma unroll
      for (int j = 0; j < 8; ++j) {
        sp[j] += __shfl_xor_sync(0xffffffffu, sp[j], msk);
        mp[j]  = fmaxf(mp[j], __shfl_xor_sync(0xffffffffu, mp[j], msk));
      }
    }
    if (kt == 0) {
      #pragma unroll
      for (int j = 0; j < 8; ++j) {
        s.sarr[pt][dt * 8 + j] = sp[j];
        s.marr[pt][dt * 8 + j] = mp[j];
      }
    }
  }
  __syncthreads();

  // ---------------- Phase 3: softmax over C, pool, residual ---------------
  const int wip = (tp >> 5);         // warp within point (0/1)
  {
    const int c = tp;
    const float sv = s.sarr[pt][c];  // b_att is softmax-invariant (scalar)
    float mx = sv;
    #pragma unroll
    for (int m = 16; m >= 1; m >>= 1)
      mx = fmaxf(mx, __shfl_xor_sync(0xffffffffu, mx, m));
    if ((tp & 31) == 0) s.redA[pt][wip] = mx;
    __syncthreads();
    mx = fmaxf(s.redA[pt][0], s.redA[pt][1]);

    const float e = expf(sv - mx);
    float se = e;
    #pragma unroll
    for (int m = 16; m >= 1; m >>= 1)
      se += __shfl_xor_sync(0xffffffffu, se, m);
    if ((tp & 31) == 0) s.redB[pt][wip] = se;
    __syncthreads();
    se = s.redB[pt][0] + s.redB[pt][1];

    const float score  = e / se;
    const float pooled = score * s.marr[pt][c];     // h2>=0, score>0
    s.resv[pt][c] = pooled + features[base_pn * CCH + c];
  }
  __syncthreads();

  // ---------------- Output GEMM + LayerNorm + ReLU ------------------------
  {
    const int o = tp;
    float acc = s.bout[o];
    #pragma unroll 8
    for (int c = 0; c < CCH; ++c)
      acc = fmaf(s.resv[pt][c], s.Wout[o][c], acc);

    float sum = acc, sq = acc * acc;
    #pragma unroll
    for (int m = 16; m >= 1; m >>= 1) {
      sum += __shfl_xor_sync(0xffffffffu, sum, m);
      sq  += __shfl_xor_sync(0xffffffffu, sq, m);
    }
    if ((tp & 31) == 0) { s.redC[pt][wip] = sum; s.redD[pt][wip] = sq; }
    __syncthreads();
    sum = s.redC[pt][0] + s.redC[pt][1];
    sq  = s.redD[pt][0] + s.redD[pt][1];

    const float mu  = sum * (1.0f / 64.0f);
    const float var = sq * (1.0f / 64.0f) - mu * mu;
    const float r   = rsqrtf(var + EPSF);
    const float y   = s.lng[o] * (acc - mu) * r + s.lnb[o];
    out[base_pn * CCH + o] = fmaxf(y, 0.0f);
  }
}

extern "C" void kernel_launch(void* const* d_in, const int* in_sizes, int n_in,
                              void* d_out, int out_size) {
  const float* points   = (const float*)d_in[0];
  const float* features = (const float*)d_in[1];
  const int*   gidx     = (const int*)  d_in[2];
  const float* W_pos    = (const float*)d_in[3];
  const float* b_pos    = (const float*)d_in[4];
  const float* bn1_g    = (const float*)d_in[5];
  const float* bn1_b    = (const float*)d_in[6];
  const float* bn1_m    = (const float*)d_in[7];
  const float* bn1_v    = (const float*)d_in[8];
  const float* W_gcm    = (const float*)d_in[9];
  const float* b_gcm    = (const float*)d_in[10];
  const float* bn2_g    = (const float*)d_in[11];
  const float* bn2_b    = (const float*)d_in[12];
  const float* bn2_m    = (const float*)d_in[13];
  const float* bn2_v    = (const float*)d_in[14];
  const float* W_att    = (const float*)d_in[15];
  // d_in[16] = b_att (scalar): softmax-invariant, unused.
  const float* W_out    = (const float*)d_in[17];
  const float* b_out    = (const float*)d_in[18];
  const float* ln_g     = (const float*)d_in[19];
  const float* ln_b     = (const float*)d_in[20];
  float* out = (float*)d_out;

  const size_t smem = sizeof(Smem);
  cudaFuncSetAttribute((const void*)bridgenet_kernel,
                       cudaFuncAttributeMaxDynamicSharedMemorySize, (int)smem);

  const int total_pts = BDIM * NPTS;          // 32768
  dim3 grid(total_pts / PPB);                 // 8192 blocks
  bridgenet_kernel<<<grid, NTHREADS, smem>>>(
      points, features, gidx, W_pos, b_pos,
      bn1_g, bn1_b, bn1_m, bn1_v,
      W_gcm, b_gcm, bn2_g, bn2_b, bn2_m, bn2_v,
      W_att, W_out, b_out, ln_g, ln_b, out);
}